// round 5
// baseline (speedup 1.0000x reference)
#include <cuda_runtime.h>
#include <cuda_bf16.h>
#include <stdint.h>

// Problem constants
#define E_TOTAL   1600000
#define N_NODES   100000
#define NODE_DIM  64
#define EDGE_DIM  32
#define IN_DIM    160     // 2*64+32
#define HID       128
#define OUT_DIM   64
#define NWARPS    16
#define NTHREADS  512
#define NPAIRS    8       // 2 warps co-compute one edge group
#define EPP       8       // edges per pair
#define TILE_E    (NPAIRS * EPP)        // 64
#define NTILES    (E_TOTAL / TILE_E)    // 25000

// smem layout (floats)
// strides ≡ 4 (mod 32) -> conflict-free lane-strided LDS.128 (lane L covers banks 4L..4L+3)
#define W1T_STRIDE 164
#define W2T_STRIDE 132
#define W1T_FLOATS (HID * W1T_STRIDE)          // 20992
#define W2T_FLOATS (OUT_DIM * W2T_STRIDE)      // 8448
#define MRG_FLOATS (NPAIRS * EPP * IN_DIM)     // 10240
#define H_FLOATS   (NPAIRS * EPP * HID)        // 8192
#define SMEM_FLOATS (W1T_FLOATS + W2T_FLOATS + MRG_FLOATS + H_FLOATS)  // 47872
#define SMEM_BYTES  (SMEM_FLOATS * 4)          // 191488

typedef unsigned long long u64;

__device__ __forceinline__ u64 fma2(u64 a, u64 b, u64 c) {
    u64 d;
    asm("fma.rn.f32x2 %0, %1, %2, %3;" : "=l"(d) : "l"(a), "l"(b), "l"(c));
    return d;
}
__device__ __forceinline__ u64 pack2(float lo, float hi) {
    u64 d;
    asm("mov.b64 %0, {%1, %2};" : "=l"(d) : "f"(lo), "f"(hi));
    return d;
}
__device__ __forceinline__ float2 unpack2(u64 v) {
    float2 r;
    asm("mov.b64 {%0, %1}, %2;" : "=f"(r.x), "=f"(r.y) : "l"(v));
    return r;
}

// edge_index dtype probe: reference declares int64 (values < 1e5 so high words all
// zero); if delivered as int32 the "high words" are random indices -> OR nonzero.
__device__ int g_idx_is32;

__global__ void detect_idx_dtype_kernel(const unsigned int* __restrict__ a) {
    unsigned v = 0;
    for (int i = threadIdx.x; i < 2048; i += blockDim.x)
        v |= a[2 * i + 1];
    int any = __syncthreads_or(v != 0);
    if (threadIdx.x == 0) g_idx_is32 = any ? 1 : 0;
}

__global__ void __launch_bounds__(NTHREADS, 1)
edge_mlp_kernel(const float* __restrict__ x,
                const float* __restrict__ ea,
                const float* __restrict__ W1,
                const float* __restrict__ b1,
                const float* __restrict__ W2,
                const float* __restrict__ b2,
                const void*  __restrict__ eidx,
                float* __restrict__ out)
{
    extern __shared__ float sm[];
    float* W1T = sm;                               // [HID][W1T_STRIDE], W1T[j][k]
    float* W2T = W1T + W1T_FLOATS;                 // [OUT][W2T_STRIDE], W2T[o][k]
    float* mergedAll = W2T + W2T_FLOATS;           // NPAIRS x [EPP][160]
    float* hAll = mergedAll + MRG_FLOATS;          // NPAIRS x [EPP][128]

    const int tid  = threadIdx.x;
    const int warp = tid >> 5;
    const int lane = tid & 31;
    const int pair = warp >> 1;       // 0..7
    const int half = warp & 1;        // j/o column half owned by this warp

    // Stage transposed weights via float4 global loads (k contiguous in smem)
    for (int i = tid; i < (IN_DIM * HID) / 4; i += NTHREADS) {
        int k = i >> 5;                 // W1 [160][128]: 32 quads per k-row
        int j4 = (i & 31) * 4;
        float4 v = ((const float4*)W1)[i];
        W1T[(j4 + 0) * W1T_STRIDE + k] = v.x;
        W1T[(j4 + 1) * W1T_STRIDE + k] = v.y;
        W1T[(j4 + 2) * W1T_STRIDE + k] = v.z;
        W1T[(j4 + 3) * W1T_STRIDE + k] = v.w;
    }
    for (int i = tid; i < (HID * OUT_DIM) / 4; i += NTHREADS) {
        int k = i >> 4;                 // W2 [128][64]: 16 quads per k-row
        int o4 = (i & 15) * 4;
        float4 v = ((const float4*)W2)[i];
        W2T[(o4 + 0) * W2T_STRIDE + k] = v.x;
        W2T[(o4 + 1) * W2T_STRIDE + k] = v.y;
        W2T[(o4 + 2) * W2T_STRIDE + k] = v.z;
        W2T[(o4 + 3) * W2T_STRIDE + k] = v.w;
    }
    __syncthreads();

    const int is32 = g_idx_is32;
    const int* e32 = (const int*)eidx;
    const long long* e64 = (const long long*)eidx;

    float* mp = mergedAll + pair * (EPP * IN_DIM);   // this pair's merged [8][160]
    float* hp = hAll + pair * (EPP * HID);           // this pair's h [8][128]

    // biases for this warp's column halves
    float b1v[2], b2v;
    b1v[0] = b1[half * 64 + lane];
    b1v[1] = b1[half * 64 + lane + 32];
    b2v    = b2[half * 32 + lane];

    const int jrow0 = (half * 64 + lane) * W1T_STRIDE;
    const int jrow1 = (half * 64 + lane + 32) * W1T_STRIDE;
    const int orow  = (half * 32 + lane) * W2T_STRIDE;

    for (int t = blockIdx.x; t < NTILES; t += gridDim.x) {
        const int ebase = t * TILE_E + pair * EPP;

        // ---- gather src/tgt indices (lanes 0..7 hold them; both warps of pair load) ----
        long long s8 = 0, t8 = 0;
        if (lane < EPP) {
            int e = ebase + lane;
            if (is32) { s8 = e32[e]; t8 = e32[E_TOTAL + e]; }
            else      { s8 = e64[e]; t8 = e64[E_TOTAL + e]; }
        }

        __syncthreads();   // prev tile's L2 reads of hp / mp done

        // ---- gather merged = [x[src] | x[tgt] | edge_attr] : 8 edges x 40 float4,
        //      64 threads of the pair cooperate (5 float4 each) ----
#pragma unroll
        for (int i = 0; i < 5; i++) {
            int idx = half * 32 + lane + 64 * i;   // 0..319
            int e = idx / 40;
            int q = idx - e * 40;
            long long se = __shfl_sync(0xffffffffu, s8, e);
            long long te = __shfl_sync(0xffffffffu, t8, e);
            float4 v;
            if (q < 16)      v = ((const float4*)(x + se * NODE_DIM))[q];
            else if (q < 32) v = ((const float4*)(x + te * NODE_DIM))[q - 16];
            else             v = ((const float4*)(ea + (long long)(ebase + e) * EDGE_DIM))[q - 32];
            *(float4*)(mp + e * IN_DIM + q * 4) = v;
        }
        __syncthreads();   // merged visible to both warps of every pair

        // ---- layer 1: h[e][j] = relu(b1[j] + sum_k merged[e][k]*W1[k][j]) ----
        // warp covers j in {half*64+lane, half*64+lane+32}; 8 edges.
        // f32x2 pairs over K: acc halves hold even-k / odd-k partial sums.
        u64 acc[EPP][2];
#pragma unroll
        for (int e = 0; e < EPP; e++) {
            acc[e][0] = pack2(b1v[0], 0.0f);
            acc[e][1] = pack2(b1v[1], 0.0f);
        }

#pragma unroll 2
        for (int kk2 = 0; kk2 < IN_DIM / 4; kk2++) {   // 40 iters, 4 k's each
            ulonglong2 w0 = *(const ulonglong2*)(W1T + jrow0 + 4 * kk2);   // LDS.128
            ulonglong2 w1 = *(const ulonglong2*)(W1T + jrow1 + 4 * kk2);
#pragma unroll
            for (int e = 0; e < EPP; e++) {
                ulonglong2 m2 = *(const ulonglong2*)(mp + e * IN_DIM + 4 * kk2);  // LDS.128 broadcast
                acc[e][0] = fma2(m2.x, w0.x, acc[e][0]);
                acc[e][0] = fma2(m2.y, w0.y, acc[e][0]);
                acc[e][1] = fma2(m2.x, w1.x, acc[e][1]);
                acc[e][1] = fma2(m2.y, w1.y, acc[e][1]);
            }
        }

        // relu, fold pair halves, store h (this warp's j-half)
#pragma unroll
        for (int e = 0; e < EPP; e++) {
            float2 p0 = unpack2(acc[e][0]);
            float2 p1 = unpack2(acc[e][1]);
            hp[e * HID + half * 64 + lane]      = fmaxf(p0.x + p0.y, 0.0f);
            hp[e * HID + half * 64 + lane + 32] = fmaxf(p1.x + p1.y, 0.0f);
        }
        __syncthreads();   // h complete for all pairs

        // ---- layer 2: out[e][o] = b2[o] + sum_k h[e][k]*W2[k][o] ----
        // warp covers o = half*32 + lane; 8 edges.
        u64 a2[EPP];
#pragma unroll
        for (int e = 0; e < EPP; e++) a2[e] = 0ull;

#pragma unroll 2
        for (int kk2 = 0; kk2 < HID / 4; kk2++) {      // 32 iters
            ulonglong2 w = *(const ulonglong2*)(W2T + orow + 4 * kk2);     // LDS.128
#pragma unroll
            for (int e = 0; e < EPP; e++) {
                ulonglong2 h2 = *(const ulonglong2*)(hp + e * HID + 4 * kk2);  // LDS.128 broadcast
                a2[e] = fma2(h2.x, w.x, a2[e]);
                a2[e] = fma2(h2.y, w.y, a2[e]);
            }
        }

        // ---- epilogue: fold halves, add bias, coalesced store ----
#pragma unroll
        for (int e = 0; e < EPP; e++) {
            float2 p = unpack2(a2[e]);
            out[(size_t)(ebase + e) * OUT_DIM + half * 32 + lane] = p.x + p.y + b2v;
        }
    }
}

extern "C" void kernel_launch(void* const* d_in, const int* in_sizes, int n_in,
                              void* d_out, int out_size)
{
    const float* x  = (const float*)d_in[0];
    const float* ea = (const float*)d_in[1];
    const float* W1 = (const float*)d_in[2];
    const float* b1 = (const float*)d_in[3];
    const float* W2 = (const float*)d_in[4];
    const float* b2 = (const float*)d_in[5];
    const void*  ei = d_in[6];
    float* out = (float*)d_out;

    cudaFuncSetAttribute(edge_mlp_kernel,
                         cudaFuncAttributeMaxDynamicSharedMemorySize, SMEM_BYTES);

    detect_idx_dtype_kernel<<<1, 256>>>((const unsigned int*)ei);
    edge_mlp_kernel<<<1472, NTHREADS, SMEM_BYTES>>>(x, ea, W1, b1, W2, b2, ei, out);
}

// round 6
// speedup vs baseline: 2.6342x; 2.6342x over previous
#include <cuda_runtime.h>
#include <cuda_bf16.h>
#include <stdint.h>

// Problem constants
#define E_TOTAL   1600000
#define N_NODES   100000
#define NODE_DIM  64
#define EDGE_DIM  32
#define IN_DIM    160
#define HID       128
#define OUT_DIM   64
#define HPRE_DIM  256          // [src-part 128 | tgt-part 128]

#define EPW       8            // edges per warp-tile
#define NTILES    (E_TOTAL / EPW)   // 200000
#define NT2       512          // kernel2 threads
#define NW2       (NT2 / 32)   // 16 warps

// kernel2 dynamic smem layout (floats)
#define W1EA_FLOATS (EDGE_DIM * HID)          // 4096  (W1 rows 128..159)
#define W2S_FLOATS  (HID * OUT_DIM)           // 8192
#define MW_FLOATS   (NW2 * EPW * EDGE_DIM)    // 4096
#define HW_FLOATS   (NW2 * EPW * HID)         // 16384
#define SM2_FLOATS  (W1EA_FLOATS + W2S_FLOATS + MW_FLOATS + HW_FLOATS)  // 32768
#define SM2_BYTES   (SM2_FLOATS * 4)          // 131072

typedef unsigned long long u64;

__device__ __forceinline__ u64 fma2(u64 a, u64 b, u64 c) {
    u64 d;
    asm("fma.rn.f32x2 %0, %1, %2, %3;" : "=l"(d) : "l"(a), "l"(b), "l"(c));
    return d;
}
__device__ __forceinline__ u64 add2(u64 a, u64 b) {
    u64 d;
    asm("add.rn.f32x2 %0, %1, %2;" : "=l"(d) : "l"(a), "l"(b));
    return d;
}
__device__ __forceinline__ u64 pack2(float lo, float hi) {
    u64 d;
    asm("mov.b64 %0, {%1, %2};" : "=l"(d) : "f"(lo), "f"(hi));
    return d;
}
__device__ __forceinline__ float2 unpack2(u64 v) {
    float2 r;
    asm("mov.b64 {%0, %1}, %2;" : "=f"(r.x), "=f"(r.y) : "l"(v));
    return r;
}

// Per-node precomputed partial activations: [n][0:128]=x[n]@W1[0:64,:], [n][128:256]=x[n]@W1[64:128,:]
__device__ float g_hpre[(size_t)N_NODES * HPRE_DIM];

// edge_index dtype probe (int64 declared; high words all zero since idx<1e5.
// If delivered int32, "high words" are random indices -> OR nonzero).
__device__ int g_idx_is32;

__global__ void detect_idx_dtype_kernel(const unsigned int* __restrict__ a) {
    unsigned v = 0;
    for (int i = threadIdx.x; i < 2048; i += blockDim.x)
        v |= a[2 * i + 1];
    int any = __syncthreads_or(v != 0);
    if (threadIdx.x == 0) g_idx_is32 = any ? 1 : 0;
}

// ---------------- kernel 1: per-node precompute (3.3 GFLOP) ----------------
// One warp per node; lane covers output quads jj=4*lane and jj=128+4*lane.
__global__ void __launch_bounds__(256, 1)
node_pre_kernel(const float* __restrict__ x, const float* __restrict__ W1)
{
    __shared__ float Wc[64 * 256];   // Wc[k][j] : j<128 -> W1[k][j], j>=128 -> W1[64+k][j-128]
    const int tid = threadIdx.x;
    for (int i = tid; i < 64 * 256; i += 256) {
        int k = i >> 8, j = i & 255;
        Wc[i] = (j < 128) ? W1[k * HID + j] : W1[(64 + k) * HID + (j - 128)];
    }
    __syncthreads();

    const int warp = tid >> 5, lane = tid & 31;
    const int gw = blockIdx.x * 8 + warp;
    const int nw = gridDim.x * 8;

    for (int n = gw; n < N_NODES; n += nw) {
        u64 acc0 = 0, acc1 = 0, acc2 = 0, acc3 = 0;
        const float4* xr = (const float4*)(x + (size_t)n * NODE_DIM);
#pragma unroll 4
        for (int c = 0; c < 16; c++) {
            float4 m = xr[c];                       // uniform LDG (L1/L2 hit)
            float mv[4] = {m.x, m.y, m.z, m.w};
#pragma unroll
            for (int k = 0; k < 4; k++) {
                int kk = 4 * c + k;
                ulonglong2 w0 = *(const ulonglong2*)(Wc + kk * 256 + 4 * lane);
                ulonglong2 w1 = *(const ulonglong2*)(Wc + kk * 256 + 128 + 4 * lane);
                u64 pk = pack2(mv[k], mv[k]);
                acc0 = fma2(pk, w0.x, acc0);
                acc1 = fma2(pk, w0.y, acc1);
                acc2 = fma2(pk, w1.x, acc2);
                acc3 = fma2(pk, w1.y, acc3);
            }
        }
        ulonglong2 s0; s0.x = acc0; s0.y = acc1;
        ulonglong2 s1; s1.x = acc2; s1.y = acc3;
        *(ulonglong2*)(g_hpre + (size_t)n * HPRE_DIM + 4 * lane) = s0;
        *(ulonglong2*)(g_hpre + (size_t)n * HPRE_DIM + 128 + 4 * lane) = s1;
    }
}

// ---------------- kernel 2: per-edge (ea GEMM + gather-add + relu + layer2) ----------------
__global__ void __launch_bounds__(NT2, 1)
edge_kernel(const float* __restrict__ ea,
            const float* __restrict__ W1,
            const float* __restrict__ b1,
            const float* __restrict__ W2,
            const float* __restrict__ b2,
            const void*  __restrict__ eidx,
            float* __restrict__ out)
{
    extern __shared__ float sm[];
    float* W1ea = sm;                    // [32][128] rows 128..159 of W1 (k-major rows)
    float* W2s  = W1ea + W1EA_FLOATS;    // [128][64] as-is
    float* mwA  = W2s + W2S_FLOATS;      // per-warp [8][32] edge_attr
    float* hwA  = mwA + MW_FLOATS;       // per-warp [8][128] h

    const int tid  = threadIdx.x;
    const int warp = tid >> 5;
    const int lane = tid & 31;

    for (int i = tid; i < W1EA_FLOATS; i += NT2) W1ea[i] = W1[128 * HID + i];
    for (int i = tid; i < W2S_FLOATS;  i += NT2) W2s[i]  = W2[i];
    __syncthreads();

    const int is32 = g_idx_is32;
    const int* e32 = (const int*)eidx;
    const long long* e64 = (const long long*)eidx;

    float* mw = mwA + warp * (EPW * EDGE_DIM);
    float* hw = hwA + warp * (EPW * HID);

    // biases: j-quad (layer1) and o-pair (layer2) for this lane
    float4 b1f = *(const float4*)(b1 + 4 * lane);
    const u64 b1q0 = pack2(b1f.x, b1f.y);
    const u64 b1q1 = pack2(b1f.z, b1f.w);
    float2 b2f = *(const float2*)(b2 + 2 * lane);
    const u64 b2q = pack2(b2f.x, b2f.y);

    const int gwarp = blockIdx.x * NW2 + warp;
    const int wstride = gridDim.x * NW2;

    for (int t = gwarp; t < NTILES; t += wstride) {
        const int ebase = t * EPW;

        // ---- edge indices: lanes 0..7 load, shfl to all ----
        int sv = 0, tv = 0;
        if (lane < EPW) {
            int e = ebase + lane;
            if (is32) { sv = e32[e]; tv = e32[E_TOTAL + e]; }
            else      { sv = (int)e64[e]; tv = (int)e64[E_TOTAL + e]; }
        }

        // ---- stage edge_attr (8 edges x 32 floats, coalesced) ----
#pragma unroll
        for (int p = 0; p < 2; p++) {
            int i = lane + 32 * p;                 // 0..63 float4s
            int e = i >> 3, q = i & 7;
            float4 v = *(const float4*)(ea + (size_t)(ebase + e) * EDGE_DIM + 4 * q);
            *(float4*)(mw + e * EDGE_DIM + 4 * q) = v;
        }
        __syncwarp();

        // ---- acc1 init: b1 + hpre_src[src] + hpre_tgt[tgt] (coalesced 512B LDG rows) ----
        u64 acc[EPW][2];
#pragma unroll
        for (int e = 0; e < EPW; e++) {
            int se = __shfl_sync(0xffffffffu, sv, e);
            int te = __shfl_sync(0xffffffffu, tv, e);
            ulonglong2 hs = *(const ulonglong2*)(g_hpre + (size_t)se * HPRE_DIM + 4 * lane);
            ulonglong2 ht = *(const ulonglong2*)(g_hpre + (size_t)te * HPRE_DIM + 128 + 4 * lane);
            acc[e][0] = add2(add2(b1q0, hs.x), ht.x);
            acc[e][1] = add2(add2(b1q1, hs.y), ht.y);
        }

        // ---- ea @ W1[128:160,:]  (32 k, j-quad per lane) ----
#pragma unroll 2
        for (int c = 0; c < EDGE_DIM / 4; c++) {   // 8 chunks of 4 k
            ulonglong2 wq[4];
#pragma unroll
            for (int k = 0; k < 4; k++)
                wq[k] = *(const ulonglong2*)(W1ea + (4 * c + k) * HID + 4 * lane);
#pragma unroll
            for (int e = 0; e < EPW; e++) {
                float4 m4 = *(const float4*)(mw + e * EDGE_DIM + 4 * c);  // broadcast
                float mv[4] = {m4.x, m4.y, m4.z, m4.w};
#pragma unroll
                for (int k = 0; k < 4; k++) {
                    u64 pk = pack2(mv[k], mv[k]);
                    acc[e][0] = fma2(pk, wq[k].x, acc[e][0]);
                    acc[e][1] = fma2(pk, wq[k].y, acc[e][1]);
                }
            }
        }

        // ---- relu, store h (j-quad coalesced STS.128) ----
#pragma unroll
        for (int e = 0; e < EPW; e++) {
            float2 p0 = unpack2(acc[e][0]);
            float2 p1 = unpack2(acc[e][1]);
            float4 hv;
            hv.x = fmaxf(p0.x, 0.0f); hv.y = fmaxf(p0.y, 0.0f);
            hv.z = fmaxf(p1.x, 0.0f); hv.w = fmaxf(p1.y, 0.0f);
            *(float4*)(hw + e * HID + 4 * lane) = hv;
        }
        __syncwarp();

        // ---- layer 2: o-pair per lane (o = 2*lane, 2*lane+1) ----
        u64 a2[EPW];
#pragma unroll
        for (int e = 0; e < EPW; e++) a2[e] = b2q;

#pragma unroll 4
        for (int c = 0; c < HID / 4; c++) {        // 32 chunks of 4 k
            u64 wv[4];
#pragma unroll
            for (int k = 0; k < 4; k++)
                wv[k] = *(const u64*)(W2s + (4 * c + k) * OUT_DIM + 2 * lane);
#pragma unroll
            for (int e = 0; e < EPW; e++) {
                float4 h4 = *(const float4*)(hw + e * HID + 4 * c);       // broadcast
                float hvv[4] = {h4.x, h4.y, h4.z, h4.w};
#pragma unroll
                for (int k = 0; k < 4; k++) {
                    u64 pk = pack2(hvv[k], hvv[k]);
                    a2[e] = fma2(pk, wv[k], a2[e]);
                }
            }
        }

        // ---- coalesced output stores (o-pair = 8B per lane) ----
#pragma unroll
        for (int e = 0; e < EPW; e++)
            *(u64*)(out + (size_t)(ebase + e) * OUT_DIM + 2 * lane) = a2[e];

        __syncwarp();   // before mw/hw reuse next tile
    }
}

extern "C" void kernel_launch(void* const* d_in, const int* in_sizes, int n_in,
                              void* d_out, int out_size)
{
    const float* x  = (const float*)d_in[0];
    const float* ea = (const float*)d_in[1];
    const float* W1 = (const float*)d_in[2];
    const float* b1 = (const float*)d_in[3];
    const float* W2 = (const float*)d_in[4];
    const float* b2 = (const float*)d_in[5];
    const void*  ei = d_in[6];
    float* out = (float*)d_out;

    cudaFuncSetAttribute(edge_kernel,
                         cudaFuncAttributeMaxDynamicSharedMemorySize, SM2_BYTES);

    detect_idx_dtype_kernel<<<1, 256>>>((const unsigned int*)ei);
    node_pre_kernel<<<1480, 256>>>(x, W1);
    edge_kernel<<<1480, NT2, SM2_BYTES>>>(ea, W1, b1, W2, b2, ei, out);
}